// round 5
// baseline (speedup 1.0000x reference)
#include <cuda_runtime.h>
#include <cuda_bf16.h>
#include <math.h>
#include <stdint.h>

// Problem constants
#define BATCH 2
#define SEQ   1024
#define HID   4096
#define NH    32
#define NKV   8
#define HD    128
#define MROWS (BATCH*SEQ)          // 2048
#define GROUPS (NH/NKV)            // 4

// ======================= warp MMA helpers (sm_80+ path) =====================
__device__ __forceinline__ uint32_t smem_u32(const void* p) {
    uint32_t a;
    asm("{ .reg .u64 t; cvta.to.shared.u64 t, %1; cvt.u32.u64 %0, t; }"
        : "=r"(a) : "l"(p));
    return a;
}

__device__ __forceinline__ void ldsm_x4(uint32_t* r, uint32_t addr) {
    asm volatile("ldmatrix.sync.aligned.m8n8.x4.shared.b16 {%0,%1,%2,%3}, [%4];"
                 : "=r"(r[0]), "=r"(r[1]), "=r"(r[2]), "=r"(r[3]) : "r"(addr));
}
__device__ __forceinline__ void ldsm_x4_t(uint32_t* r, uint32_t addr) {
    asm volatile("ldmatrix.sync.aligned.m8n8.x4.trans.shared.b16 {%0,%1,%2,%3}, [%4];"
                 : "=r"(r[0]), "=r"(r[1]), "=r"(r[2]), "=r"(r[3]) : "r"(addr));
}

__device__ __forceinline__ void mma16816(float* d, const uint32_t* a,
                                         const uint32_t* b) {
    asm volatile("mma.sync.aligned.m16n8k16.row.col.f32.bf16.bf16.f32 "
                 "{%0,%1,%2,%3}, {%4,%5,%6,%7}, {%8,%9}, {%0,%1,%2,%3};"
                 : "+f"(d[0]), "+f"(d[1]), "+f"(d[2]), "+f"(d[3])
                 : "r"(a[0]), "r"(a[1]), "r"(a[2]), "r"(a[3]),
                   "r"(b[0]), "r"(b[1]));
}

#define CP_ASYNC16(smem, gptr) \
    asm volatile("cp.async.cg.shared.global [%0], [%1], 16;" \
                 :: "r"(smem), "l"(gptr))
#define CP_COMMIT() asm volatile("cp.async.commit_group;" ::: "memory")
#define CP_WAIT(N)  asm volatile("cp.async.wait_group %0;" :: "n"(N) : "memory")

// ---------------- scratch (device globals; no cudaMalloc allowed) ----------
__device__ float g_q[(size_t)MROWS * NH * HD];
__device__ float g_k[(size_t)MROWS * NKV * HD];

__device__ __nv_bfloat16 g_xhi[(size_t)MROWS * HID];
__device__ __nv_bfloat16 g_xlo[(size_t)MROWS * HID];
__device__ __nv_bfloat16 g_ahi[(size_t)MROWS * HID];
__device__ __nv_bfloat16 g_alo[(size_t)MROWS * HID];
__device__ __nv_bfloat16 g_wqhiT[(size_t)HID * HID];
__device__ __nv_bfloat16 g_wqloT[(size_t)HID * HID];
__device__ __nv_bfloat16 g_wkhiT[(size_t)(NKV*HD) * HID];
__device__ __nv_bfloat16 g_wkloT[(size_t)(NKV*HD) * HID];
__device__ __nv_bfloat16 g_wvhiT[(size_t)(NKV*HD) * HID];
__device__ __nv_bfloat16 g_wvloT[(size_t)(NKV*HD) * HID];
__device__ __nv_bfloat16 g_wohiT[(size_t)HID * HID];
__device__ __nv_bfloat16 g_woloT[(size_t)HID * HID];

// bf16 attention operands (post-RoPE)
__device__ __nv_bfloat16 g_qh[(size_t)MROWS * NH * HD];
__device__ __nv_bfloat16 g_ql[(size_t)MROWS * NH * HD];
__device__ __nv_bfloat16 g_kh[(size_t)MROWS * NKV * HD];
__device__ __nv_bfloat16 g_kl[(size_t)MROWS * NKV * HD];
__device__ __nv_bfloat16 g_vh[(size_t)MROWS * NKV * HD];
__device__ __nv_bfloat16 g_vl[(size_t)MROWS * NKV * HD];

// ---------------- fp32 -> bf16 hi/lo split (elementwise) --------------------
__global__ void split_kernel(const float4* __restrict__ in,
                             ushort4* __restrict__ hi,
                             ushort4* __restrict__ lo, int n4)
{
    int i = blockIdx.x * blockDim.x + threadIdx.x;
    if (i >= n4) return;
    float4 v = in[i];
    __nv_bfloat16 h0 = __float2bfloat16(v.x);
    __nv_bfloat16 h1 = __float2bfloat16(v.y);
    __nv_bfloat16 h2 = __float2bfloat16(v.z);
    __nv_bfloat16 h3 = __float2bfloat16(v.w);
    __nv_bfloat16 l0 = __float2bfloat16(v.x - __bfloat162float(h0));
    __nv_bfloat16 l1 = __float2bfloat16(v.y - __bfloat162float(h1));
    __nv_bfloat16 l2 = __float2bfloat16(v.z - __bfloat162float(h2));
    __nv_bfloat16 l3 = __float2bfloat16(v.w - __bfloat162float(h3));
    ushort4 H = {__bfloat16_as_ushort(h0), __bfloat16_as_ushort(h1),
                 __bfloat16_as_ushort(h2), __bfloat16_as_ushort(h3)};
    ushort4 L = {__bfloat16_as_ushort(l0), __bfloat16_as_ushort(l1),
                 __bfloat16_as_ushort(l2), __bfloat16_as_ushort(l3)};
    hi[i] = H;
    lo[i] = L;
}

// ------------- fp32 [K,N] -> transposed bf16 hi/lo [N,K] --------------------
__global__ __launch_bounds__(256) void splitT_kernel(
    const float* __restrict__ W,
    __nv_bfloat16* __restrict__ hiT, __nv_bfloat16* __restrict__ loT,
    int K, int N)
{
    __shared__ float tile[32][33];
    const int tx = threadIdx.x;
    const int ty = threadIdx.y;
    const int n0 = blockIdx.x * 32;
    const int k0 = blockIdx.y * 32;
    #pragma unroll
    for (int i = 0; i < 4; i++)
        tile[ty + 8*i][tx] = W[(size_t)(k0 + ty + 8*i) * N + n0 + tx];
    __syncthreads();
    #pragma unroll
    for (int i = 0; i < 4; i++) {
        float v = tile[tx][ty + 8*i];
        __nv_bfloat16 h = __float2bfloat16(v);
        __nv_bfloat16 l = __float2bfloat16(v - __bfloat162float(h));
        size_t o = (size_t)(n0 + ty + 8*i) * K + k0 + tx;
        hiT[o] = h;
        loT[o] = l;
    }
}

// ------------- fused RoPE + prescale + bf16 hi/lo split ---------------------
__global__ void rope_split_kernel(const float* __restrict__ src,
                                  __nv_bfloat16* __restrict__ hi,
                                  __nv_bfloat16* __restrict__ lo,
                                  const float* __restrict__ fcos,
                                  const float* __restrict__ fsin,
                                  int nheads, float prescale, int total_pairs)
{
    int idx = blockIdx.x * blockDim.x + threadIdx.x;
    if (idx >= total_pairs) return;
    int d = idx & 63;
    int row = idx >> 6;
    int s = (row / nheads) % SEQ;
    size_t base = (size_t)row * HD;
    float c  = fcos[s * 64 + d];
    float sn = fsin[s * 64 + d];
    float t1 = src[base + d];
    float t2 = src[base + 64 + d];
    float r1 = (t1 * c  - t2 * sn) * prescale;
    float r2 = (t1 * sn + t2 * c)  * prescale;
    __nv_bfloat16 h1 = __float2bfloat16(r1);
    __nv_bfloat16 h2 = __float2bfloat16(r2);
    hi[base + d]      = h1;
    hi[base + 64 + d] = h2;
    lo[base + d]      = __float2bfloat16(r1 - __bfloat162float(h1));
    lo[base + 64 + d] = __float2bfloat16(r2 - __bfloat162float(h2));
}

// ---------------- warp-MMA GEMM: C[M,N] = A @ B^T (3-term bf16 split) -------
// 3-stage cp.async pipeline. Optional fused bf16 hi/lo epilogue.
#define BK 32
#define ROWB 80
#define TILE_B (128 * ROWB)
#define STAGE_B (4 * TILE_B)           // 40960
#define GSMEM_BYTES (3 * STAGE_B)      // 122880

__global__ __launch_bounds__(256, 1) void gemm3_kernel(
    const __nv_bfloat16* __restrict__ Ahi, const __nv_bfloat16* __restrict__ Alo,
    const __nv_bfloat16* __restrict__ Bhi, const __nv_bfloat16* __restrict__ Blo,
    float* __restrict__ C,
    __nv_bfloat16* __restrict__ Chi, __nv_bfloat16* __restrict__ Clo,
    int M, int N, int K)
{
    extern __shared__ char sb[];
    const uint32_t sbase = smem_u32(sb);
    const int tid = threadIdx.x;
    const int wid = tid >> 5;
    const int lid = tid & 31;
    const int wm = wid & 3;
    const int wn = wid >> 2;

    const int row0 = blockIdx.y * 128;
    const int col0 = blockIdx.x * 128;

    const __nv_bfloat16* gp[4] = {
        Ahi + (size_t)row0 * K, Alo + (size_t)row0 * K,
        Bhi + (size_t)col0 * K, Blo + (size_t)col0 * K
    };

    float acc[2][8][4];
    #pragma unroll
    for (int mi = 0; mi < 2; mi++)
        #pragma unroll
        for (int g = 0; g < 8; g++)
            #pragma unroll
            for (int e = 0; e < 4; e++) acc[mi][g][e] = 0.f;

    const int a_row = lid & 15;
    const int a_kx  = (lid >> 4) << 3;
    const int b_row = (lid & 7) + ((lid >> 4) << 3);
    const int b_kx  = ((lid >> 3) & 1) << 3;

    const int nkc = K / BK;

    // prefetch stages 0,1
    #pragma unroll
    for (int ps = 0; ps < 2; ps++) {
        int k0 = ps * BK;
        uint32_t stg = sbase + ps * STAGE_B;
        #pragma unroll
        for (int i = 0; i < 8; i++) {
            int chunk = tid + i * 256;
            int tile = chunk >> 9;
            int w = chunk & 511;
            int r = w >> 2, c = w & 3;
            const __nv_bfloat16* g = gp[tile] + (size_t)r * K + k0 + c * 8;
            CP_ASYNC16(stg + tile * TILE_B + r * ROWB + c * 16, g);
        }
        CP_COMMIT();
    }

    int buf = 0;
    for (int kc = 0; kc < nkc; kc++) {
        if (kc + 2 < nkc) {
            int k0 = (kc + 2) * BK;
            int pb = buf + 2; if (pb >= 3) pb -= 3;
            uint32_t stg = sbase + pb * STAGE_B;
            #pragma unroll
            for (int i = 0; i < 8; i++) {
                int chunk = tid + i * 256;
                int tile = chunk >> 9;
                int w = chunk & 511;
                int r = w >> 2, c = w & 3;
                const __nv_bfloat16* g = gp[tile] + (size_t)r * K + k0 + c * 8;
                CP_ASYNC16(stg + tile * TILE_B + r * ROWB + c * 16, g);
            }
            CP_COMMIT();
            CP_WAIT(2);
        } else if (kc + 1 < nkc) {
            CP_WAIT(1);
        } else {
            CP_WAIT(0);
        }
        __syncthreads();

        const uint32_t st = sbase + buf * STAGE_B;
        #pragma unroll
        for (int ks = 0; ks < 2; ks++) {
            const int k0 = ks * 16;
            uint32_t ah[2][4], al[2][4];
            #pragma unroll
            for (int mi = 0; mi < 2; mi++) {
                uint32_t aoff = (uint32_t)((wm * 32 + mi * 16 + a_row) * ROWB
                                           + (k0 + a_kx) * 2);
                ldsm_x4(ah[mi], st + aoff);
                ldsm_x4(al[mi], st + TILE_B + aoff);
            }
            #pragma unroll
            for (int g4 = 0; g4 < 4; g4++) {
                uint32_t bh[4], bl[4];
                uint32_t boff = (uint32_t)((wn * 64 + g4 * 16 + b_row) * ROWB
                                           + (k0 + b_kx) * 2);
                ldsm_x4(bh, st + 2 * TILE_B + boff);
                ldsm_x4(bl, st + 3 * TILE_B + boff);
                #pragma unroll
                for (int mi = 0; mi < 2; mi++) {
                    #pragma unroll
                    for (int sub = 0; sub < 2; sub++) {
                        float* d = acc[mi][g4 * 2 + sub];
                        mma16816(d, ah[mi], bh + sub * 2);
                        mma16816(d, ah[mi], bl + sub * 2);
                        mma16816(d, al[mi], bh + sub * 2);
                    }
                }
            }
        }
        __syncthreads();
        if (++buf == 3) buf = 0;
    }

    const int cr = lid >> 2;
    const int cc = (lid & 3) * 2;
    #pragma unroll
    for (int mi = 0; mi < 2; mi++) {
        #pragma unroll
        for (int g = 0; g < 8; g++) {
            int rg = row0 + wm * 32 + mi * 16 + cr;
            int cg = col0 + wn * 64 + g * 8 + cc;
            if (C) {
                float2 v0 = {acc[mi][g][0], acc[mi][g][1]};
                float2 v1 = {acc[mi][g][2], acc[mi][g][3]};
                *(float2*)(C + (size_t)rg * N + cg)       = v0;
                *(float2*)(C + (size_t)(rg + 8) * N + cg) = v1;
            }
            if (Chi) {
                #pragma unroll
                for (int half = 0; half < 2; half++) {
                    float e0 = acc[mi][g][half * 2];
                    float e1 = acc[mi][g][half * 2 + 1];
                    __nv_bfloat162 h = __floats2bfloat162_rn(e0, e1);
                    float r0 = e0 - __bfloat162float(__low2bfloat16(h));
                    float r1 = e1 - __bfloat162float(__high2bfloat16(h));
                    __nv_bfloat162 l = __floats2bfloat162_rn(r0, r1);
                    size_t o = (size_t)(rg + half * 8) * N + cg;
                    *(__nv_bfloat162*)(Chi + o) = h;
                    *(__nv_bfloat162*)(Clo + o) = l;
                }
            }
        }
    }
}

// ---------------- Flash attention, HMMA (causal, GQA) -----------------------
// Q/K 3-term, P/V 3-term. Writes bf16 hi/lo output directly.
#define FROWB 272
#define FQ_TILE (128 * FROWB)
#define FKV_TILE (64 * FROWB)
#define FSTAGE (4 * FKV_TILE)
#define FSMEM (2 * FQ_TILE + 2 * FSTAGE)   // 208896

__global__ __launch_bounds__(256, 1) void flash_mma_kernel(
    const __nv_bfloat16* __restrict__ Qh, const __nv_bfloat16* __restrict__ Ql,
    const __nv_bfloat16* __restrict__ Kh, const __nv_bfloat16* __restrict__ Kl,
    const __nv_bfloat16* __restrict__ Vh, const __nv_bfloat16* __restrict__ Vl,
    __nv_bfloat16* __restrict__ Ohi, __nv_bfloat16* __restrict__ Olo)
{
    extern __shared__ char sb[];
    const uint32_t smq = smem_u32(sb);
    const uint32_t smkv = smq + 2 * FQ_TILE;

    const int qb  = blockIdx.x;
    const int h   = blockIdx.y;
    const int b   = blockIdx.z;
    const int kvh = h / GROUPS;
    const int tid = threadIdx.x;
    const int wid = tid >> 5;
    const int lid = tid & 31;

    {
        const __nv_bfloat16* qsrc[2] = {
            Qh + ((size_t)(b * SEQ + qb * 128) * NH + h) * HD,
            Ql + ((size_t)(b * SEQ + qb * 128) * NH + h) * HD
        };
        #pragma unroll
        for (int i = 0; i < 16; i++) {
            int chunk = tid + i * 256;
            int t = chunk >> 11;
            int w = chunk & 2047;
            int r = w >> 4, x = w & 15;
            const __nv_bfloat16* g = qsrc[t] + (size_t)r * NH * HD + x * 8;
            CP_ASYNC16(smq + t * FQ_TILE + r * FROWB + x * 16, g);
        }
        CP_COMMIT();
    }

    const __nv_bfloat16* kvsrc[4] = {
        Kh + ((size_t)(b * SEQ) * NKV + kvh) * HD,
        Kl + ((size_t)(b * SEQ) * NKV + kvh) * HD,
        Vh + ((size_t)(b * SEQ) * NKV + kvh) * HD,
        Vl + ((size_t)(b * SEQ) * NKV + kvh) * HD
    };

    const int nkt = 2 * qb + 2;

    {
        #pragma unroll
        for (int i = 0; i < 16; i++) {
            int chunk = tid + i * 256;
            int t = chunk >> 10;
            int w = chunk & 1023;
            int r = w >> 4, x = w & 15;
            const __nv_bfloat16* g = kvsrc[t] + (size_t)r * NKV * HD + x * 8;
            CP_ASYNC16(smkv + t * FKV_TILE + r * FROWB + x * 16, g);
        }
        CP_COMMIT();
    }

    const int Q0 = wid * 16;
    const int r0 = lid >> 2;
    const int c0 = (lid & 3) * 2;
    float m0 = -1e30f, m1 = -1e30f, l0 = 0.f, l1 = 0.f;
    float acc_o[16][4];
    #pragma unroll
    for (int t = 0; t < 16; t++)
        #pragma unroll
        for (int e = 0; e < 4; e++) acc_o[t][e] = 0.f;

    const int a_row = lid & 15;
    const int a_kx  = (lid >> 4) << 3;
    const int b_row = (lid & 7) + ((lid >> 4) << 3);
    const int b_kx  = ((lid >> 3) & 1) << 3;

    for (int kt = 0; kt < nkt; kt++) {
        __syncthreads();
        if (kt + 1 < nkt) {
            int k0r = (kt + 1) * 64;
            uint32_t stg = smkv + ((kt + 1) & 1) * FSTAGE;
            #pragma unroll
            for (int i = 0; i < 16; i++) {
                int chunk = tid + i * 256;
                int t = chunk >> 10;
                int w = chunk & 1023;
                int r = w >> 4, x = w & 15;
                const __nv_bfloat16* g = kvsrc[t]
                    + (size_t)(k0r + r) * NKV * HD + x * 8;
                CP_ASYNC16(stg + t * FKV_TILE + r * FROWB + x * 16, g);
            }
            CP_COMMIT();
            CP_WAIT(1);
        } else {
            CP_WAIT(0);
        }
        __syncthreads();

        const uint32_t skh = smkv + (kt & 1) * FSTAGE;
        const uint32_t skl = skh + FKV_TILE;
        const uint32_t svh = skh + 2 * FKV_TILE;
        const uint32_t svl = skh + 3 * FKV_TILE;

        // ---- S = Q K^T (3-term) ----
        float s_acc[8][4];
        #pragma unroll
        for (int t = 0; t < 8; t++)
            #pragma unroll
            for (int e = 0; e < 4; e++) s_acc[t][e] = 0.f;

        #pragma unroll
        for (int kt8 = 0; kt8 < 8; kt8++) {
            uint32_t ah[4], al[4];
            uint32_t aoff = (uint32_t)((Q0 + a_row) * FROWB + (kt8 * 16 + a_kx) * 2);
            ldsm_x4(ah, smq + aoff);
            ldsm_x4(al, smq + FQ_TILE + aoff);
            #pragma unroll
            for (int ng = 0; ng < 4; ng++) {
                uint32_t bh[4], bl[4];
                uint32_t boff = (uint32_t)((ng * 16 + b_row) * FROWB
                                           + (kt8 * 16 + b_kx) * 2);
                ldsm_x4(bh, skh + boff);
                ldsm_x4(bl, skl + boff);
                #pragma unroll
                for (int sub = 0; sub < 2; sub++) {
                    float* d = s_acc[ng * 2 + sub];
                    mma16816(d, ah, bh + sub * 2);
                    mma16816(d, ah, bl + sub * 2);
                    mma16816(d, al, bh + sub * 2);
                }
            }
        }

        // ---- causal mask ----
        const int k0 = kt * 64;
        const int qg0 = qb * 128 + Q0 + r0;
        if (k0 + 63 > qb * 128 + Q0) {
            #pragma unroll
            for (int t = 0; t < 8; t++) {
                int kc = k0 + t * 8 + c0;
                if (kc     > qg0)     s_acc[t][0] = -1e30f;
                if (kc + 1 > qg0)     s_acc[t][1] = -1e30f;
                if (kc     > qg0 + 8) s_acc[t][2] = -1e30f;
                if (kc + 1 > qg0 + 8) s_acc[t][3] = -1e30f;
            }
        }

        // ---- online softmax (scores pre-scaled by 1/sqrt(d)*log2e) ----
        float mx0 = -1e30f, mx1 = -1e30f;
        #pragma unroll
        for (int t = 0; t < 8; t++) {
            mx0 = fmaxf(mx0, fmaxf(s_acc[t][0], s_acc[t][1]));
            mx1 = fmaxf(mx1, fmaxf(s_acc[t][2], s_acc[t][3]));
        }
        mx0 = fmaxf(mx0, __shfl_xor_sync(0xffffffffu, mx0, 1));
        mx0 = fmaxf(mx0, __shfl_xor_sync(0xffffffffu, mx0, 2));
        mx1 = fmaxf(mx1, __shfl_xor_sync(0xffffffffu, mx1, 1));
        mx1 = fmaxf(mx1, __shfl_xor_sync(0xffffffffu, mx1, 2));
        float mn0 = fmaxf(m0, mx0);
        float mn1 = fmaxf(m1, mx1);
        float e0 = exp2f(m0 - mn0);
        float e1 = exp2f(m1 - mn1);
        float rs0 = 0.f, rs1 = 0.f;
        #pragma unroll
        for (int t = 0; t < 8; t++) {
            s_acc[t][0] = exp2f(s_acc[t][0] - mn0);
            s_acc[t][1] = exp2f(s_acc[t][1] - mn0);
            s_acc[t][2] = exp2f(s_acc[t][2] - mn1);
            s_acc[t][3] = exp2f(s_acc[t][3] - mn1);
            rs0 += s_acc[t][0] + s_acc[t][1];
            rs1 += s_acc[t][2] + s_acc[t][3];
        }
        rs0 += __shfl_xor_sync(0xffffffffu, rs0, 1);
        rs0 += __shfl_xor_sync(0xffffffffu, rs0, 2);
        rs1 += __shfl_xor_sync(0xffffffffu, rs1, 1);
        rs1 += __shfl_xor_sync(0xffffffffu, rs1, 2);
        l0 = l0 * e0 + rs0;
        l1 = l1 * e1 + rs1;
        m0 = mn0;
        m1 = mn1;
        #pragma unroll
        for (int t = 0; t < 16; t++) {
            acc_o[t][0] *= e0;
            acc_o[t][1] *= e0;
            acc_o[t][2] *= e1;
            acc_o[t][3] *= e1;
        }

        // ---- O += P V (3-term: Phi*Vhi + Phi*Vlo + Plo*Vhi) ----
        #pragma unroll
        for (int ktv = 0; ktv < 4; ktv++) {
            uint32_t a[4], ar[4];
            #pragma unroll
            for (int pe = 0; pe < 4; pe++) {
                float x0 = s_acc[2*ktv + (pe >> 1)][(pe & 1) ? 2 : 0];
                float x1 = s_acc[2*ktv + (pe >> 1)][(pe & 1) ? 3 : 1];
                __nv_bfloat162 hh = __floats2bfloat162_rn(x0, x1);
                float q0 = x0 - __bfloat162float(__low2bfloat16(hh));
                float q1 = x1 - __bfloat162float(__high2bfloat16(hh));
                __nv_bfloat162 ll = __floats2bfloat162_rn(q0, q1);
                a[pe]  = *(uint32_t*)&hh;
                ar[pe] = *(uint32_t*)&ll;
            }
            // fragment order fix: a[] must be (row0 k0-1, row8 k0-1, row0 k8-9, row8 k8-9)
            // pe mapping above gives: pe0=(r0,k t2v), pe1=(r8,..) per s_acc layout
            #pragma unroll
            for (int ng = 0; ng < 8; ng++) {
                uint32_t voff = (uint32_t)((ktv * 16 + (lid & 15)) * FROWB
                                           + (ng * 16 + ((lid >> 4) << 3)) * 2);
                uint32_t bh[4], bl[4];
                ldsm_x4_t(bh, svh + voff);
                ldsm_x4_t(bl, svl + voff);
                mma16816(acc_o[ng * 2],     a, bh);
                mma16816(acc_o[ng * 2 + 1], a, bh + 2);
                mma16816(acc_o[ng * 2],     a, bl);
                mma16816(acc_o[ng * 2 + 1], a, bl + 2);
                mma16816(acc_o[ng * 2],     ar, bh);
                mma16816(acc_o[ng * 2 + 1], ar, bh + 2);
            }
        }
    }

    // ---- normalize + write bf16 hi/lo out ----
    const float li0 = 1.f / l0;
    const float li1 = 1.f / l1;
    const size_t obase = ((size_t)(b * SEQ + qb * 128 + Q0) * NH + h) * HD;
    #pragma unroll
    for (int t = 0; t < 16; t++) {
        float e00 = acc_o[t][0] * li0, e01 = acc_o[t][1] * li0;
        float e10 = acc_o[t][2] * li1, e11 = acc_o[t][3] * li1;
        __nv_bfloat162 h0 = __floats2bfloat162_rn(e00, e01);
        __nv_bfloat162 h1 = __floats2bfloat162_rn(e10, e11);
        __nv_bfloat162 l0v = __floats2bfloat162_rn(
            e00 - __bfloat162float(__low2bfloat16(h0)),
            e01 - __bfloat162float(__high2bfloat16(h0)));
        __nv_bfloat162 l1v = __floats2bfloat162_rn(
            e10 - __bfloat162float(__low2bfloat16(h1)),
            e11 - __bfloat162float(__high2bfloat16(h1)));
        size_t o0 = obase + (size_t)r0 * NH * HD + t * 8 + c0;
        size_t o1 = obase + (size_t)(r0 + 8) * NH * HD + t * 8 + c0;
        *(__nv_bfloat162*)(Ohi + o0) = h0;
        *(__nv_bfloat162*)(Olo + o0) = l0v;
        *(__nv_bfloat162*)(Ohi + o1) = h1;
        *(__nv_bfloat162*)(Olo + o1) = l1v;
    }
}

// ---------------- launch ----------------------------------------------------
template <typename T>
static T* sym_addr(const void* sym)
{
    void* p = nullptr;
    cudaGetSymbolAddress(&p, sym);
    return (T*)p;
}

extern "C" void kernel_launch(void* const* d_in, const int* in_sizes, int n_in,
                              void* d_out, int out_size)
{
    const float* x    = (const float*)d_in[0];
    const float* wq   = (const float*)d_in[1];
    const float* wk   = (const float*)d_in[2];
    const float* wv   = (const float*)d_in[3];
    const float* wo   = (const float*)d_in[4];
    const float* fcos = (const float*)d_in[5];
    const float* fsin = (const float*)d_in[6];
    float* out = (float*)d_out;

    float* q    = sym_addr<float>(g_q);
    float* k    = sym_addr<float>(g_k);
    __nv_bfloat16* xhi  = sym_addr<__nv_bfloat16>(g_xhi);
    __nv_bfloat16* xlo  = sym_addr<__nv_bfloat16>(g_xlo);
    __nv_bfloat16* ahi  = sym_addr<__nv_bfloat16>(g_ahi);
    __nv_bfloat16* alo  = sym_addr<__nv_bfloat16>(g_alo);
    __nv_bfloat16* wqh  = sym_addr<__nv_bfloat16>(g_wqhiT);
    __nv_bfloat16* wql  = sym_addr<__nv_bfloat16>(g_wqloT);
    __nv_bfloat16* wkh  = sym_addr<__nv_bfloat16>(g_wkhiT);
    __nv_bfloat16* wkl  = sym_addr<__nv_bfloat16>(g_wkloT);
    __nv_bfloat16* wvh  = sym_addr<__nv_bfloat16>(g_wvhiT);
    __nv_bfloat16* wvl  = sym_addr<__nv_bfloat16>(g_wvloT);
    __nv_bfloat16* woh  = sym_addr<__nv_bfloat16>(g_wohiT);
    __nv_bfloat16* wol  = sym_addr<__nv_bfloat16>(g_woloT);
    __nv_bfloat16* qh = sym_addr<__nv_bfloat16>(g_qh);
    __nv_bfloat16* ql = sym_addr<__nv_bfloat16>(g_ql);
    __nv_bfloat16* kh = sym_addr<__nv_bfloat16>(g_kh);
    __nv_bfloat16* kl = sym_addr<__nv_bfloat16>(g_kl);
    __nv_bfloat16* vh = sym_addr<__nv_bfloat16>(g_vh);
    __nv_bfloat16* vl = sym_addr<__nv_bfloat16>(g_vl);

    static bool attrs_set = false;
    if (!attrs_set) {
        cudaFuncSetAttribute(gemm3_kernel,
                             cudaFuncAttributeMaxDynamicSharedMemorySize, GSMEM_BYTES);
        cudaFuncSetAttribute(flash_mma_kernel,
                             cudaFuncAttributeMaxDynamicSharedMemorySize, FSMEM);
        attrs_set = true;
    }

    // Split/transpose conversions
    {
        int n4 = MROWS * HID / 4;
        split_kernel<<<(n4 + 255) / 256, 256>>>((const float4*)x,
                                                (ushort4*)xhi, (ushort4*)xlo, n4);
        splitT_kernel<<<dim3(HID/32, HID/32), dim3(32,8)>>>(wq, wqh, wql, HID, HID);
        splitT_kernel<<<dim3((NKV*HD)/32, HID/32), dim3(32,8)>>>(wk, wkh, wkl, HID, NKV*HD);
        splitT_kernel<<<dim3((NKV*HD)/32, HID/32), dim3(32,8)>>>(wv, wvh, wvl, HID, NKV*HD);
        splitT_kernel<<<dim3(HID/32, HID/32), dim3(32,8)>>>(wo, woh, wol, HID, HID);
    }

    // QKV projections (tensor cores, 3-term bf16)
    gemm3_kernel<<<dim3((NH*HD)/128, MROWS/128), 256, GSMEM_BYTES>>>(
        xhi, xlo, wqh, wql, q, nullptr, nullptr, MROWS, NH*HD, HID);
    gemm3_kernel<<<dim3((NKV*HD)/128, MROWS/128), 256, GSMEM_BYTES>>>(
        xhi, xlo, wkh, wkl, k, nullptr, nullptr, MROWS, NKV*HD, HID);
    // V projection: fused bf16 hi/lo epilogue (no fp32 V, no split pass)
    gemm3_kernel<<<dim3((NKV*HD)/128, MROWS/128), 256, GSMEM_BYTES>>>(
        xhi, xlo, wvh, wvl, nullptr, vh, vl, MROWS, NKV*HD, HID);

    // RoPE + prescale + split to bf16 hi/lo
    {
        const float qscale = 0.08838834764831845f * 1.4426950408889634f; // 1/sqrt(128)*log2e
        int pq = MROWS * NH * 64;
        int pk = MROWS * NKV * 64;
        rope_split_kernel<<<(pq + 255) / 256, 256>>>(q, qh, ql, fcos, fsin, NH, qscale, pq);
        rope_split_kernel<<<(pk + 255) / 256, 256>>>(k, kh, kl, fcos, fsin, NKV, 1.0f, pk);
    }

    // Flash attention (HMMA), writes bf16 hi/lo directly
    flash_mma_kernel<<<dim3(SEQ / 128, NH, BATCH), 256, FSMEM>>>(
        qh, ql, kh, kl, vh, vl, ahi, alo);

    // Output projection
    gemm3_kernel<<<dim3(HID/128, MROWS/128), 256, GSMEM_BYTES>>>(
        ahi, alo, woh, wol, out, nullptr, nullptr, MROWS, HID, HID);
}

// round 6
// speedup vs baseline: 1.1332x; 1.1332x over previous
#include <cuda_runtime.h>
#include <cuda_bf16.h>
#include <math.h>
#include <stdint.h>

// Problem constants
#define BATCH 2
#define SEQ   1024
#define HID   4096
#define NH    32
#define NKV   8
#define HD    128
#define MROWS (BATCH*SEQ)          // 2048
#define GROUPS (NH/NKV)            // 4
#define NQKV  (HID + 2*NKV*HD)     // 6144 (q 0..4095, k 4096..5119, v 5120..6143)

// ======================= warp MMA helpers (sm_80+ path) =====================
__device__ __forceinline__ uint32_t smem_u32(const void* p) {
    uint32_t a;
    asm("{ .reg .u64 t; cvta.to.shared.u64 t, %1; cvt.u32.u64 %0, t; }"
        : "=r"(a) : "l"(p));
    return a;
}

__device__ __forceinline__ void ldsm_x4(uint32_t* r, uint32_t addr) {
    asm volatile("ldmatrix.sync.aligned.m8n8.x4.shared.b16 {%0,%1,%2,%3}, [%4];"
                 : "=r"(r[0]), "=r"(r[1]), "=r"(r[2]), "=r"(r[3]) : "r"(addr));
}
__device__ __forceinline__ void ldsm_x4_t(uint32_t* r, uint32_t addr) {
    asm volatile("ldmatrix.sync.aligned.m8n8.x4.trans.shared.b16 {%0,%1,%2,%3}, [%4];"
                 : "=r"(r[0]), "=r"(r[1]), "=r"(r[2]), "=r"(r[3]) : "r"(addr));
}

__device__ __forceinline__ void mma16816(float* d, const uint32_t* a,
                                         const uint32_t* b) {
    asm volatile("mma.sync.aligned.m16n8k16.row.col.f32.bf16.bf16.f32 "
                 "{%0,%1,%2,%3}, {%4,%5,%6,%7}, {%8,%9}, {%0,%1,%2,%3};"
                 : "+f"(d[0]), "+f"(d[1]), "+f"(d[2]), "+f"(d[3])
                 : "r"(a[0]), "r"(a[1]), "r"(a[2]), "r"(a[3]),
                   "r"(b[0]), "r"(b[1]));
}

#define CP_ASYNC16(smem, gptr) \
    asm volatile("cp.async.cg.shared.global [%0], [%1], 16;" \
                 :: "r"(smem), "l"(gptr))
#define CP_COMMIT() asm volatile("cp.async.commit_group;" ::: "memory")
#define CP_WAIT(N)  asm volatile("cp.async.wait_group %0;" :: "n"(N) : "memory")

// ---------------- scratch (device globals; no cudaMalloc allowed) ----------
__device__ float g_qkv[(size_t)MROWS * NQKV];       // fused QKV output (fp32)

__device__ __nv_bfloat16 g_xhi[(size_t)MROWS * HID];
__device__ __nv_bfloat16 g_xlo[(size_t)MROWS * HID];
__device__ __nv_bfloat16 g_ahi[(size_t)MROWS * HID];
__device__ __nv_bfloat16 g_alo[(size_t)MROWS * HID];
__device__ __nv_bfloat16 g_wqkvhiT[(size_t)NQKV * HID];   // [6144, 4096]
__device__ __nv_bfloat16 g_wqkvloT[(size_t)NQKV * HID];
__device__ __nv_bfloat16 g_wohiT[(size_t)HID * HID];
__device__ __nv_bfloat16 g_woloT[(size_t)HID * HID];

// bf16 attention operands (post-RoPE)
__device__ __nv_bfloat16 g_qh[(size_t)MROWS * NH * HD];
__device__ __nv_bfloat16 g_ql[(size_t)MROWS * NH * HD];
__device__ __nv_bfloat16 g_kh[(size_t)MROWS * NKV * HD];
__device__ __nv_bfloat16 g_kl[(size_t)MROWS * NKV * HD];
__device__ __nv_bfloat16 g_vh[(size_t)MROWS * NKV * HD];
__device__ __nv_bfloat16 g_vl[(size_t)MROWS * NKV * HD];

// ---------------- fp32 -> bf16 hi/lo split (elementwise) --------------------
__global__ void split_kernel(const float4* __restrict__ in,
                             ushort4* __restrict__ hi,
                             ushort4* __restrict__ lo, int n4)
{
    int i = blockIdx.x * blockDim.x + threadIdx.x;
    if (i >= n4) return;
    float4 v = in[i];
    __nv_bfloat16 h0 = __float2bfloat16(v.x);
    __nv_bfloat16 h1 = __float2bfloat16(v.y);
    __nv_bfloat16 h2 = __float2bfloat16(v.z);
    __nv_bfloat16 h3 = __float2bfloat16(v.w);
    __nv_bfloat16 l0 = __float2bfloat16(v.x - __bfloat162float(h0));
    __nv_bfloat16 l1 = __float2bfloat16(v.y - __bfloat162float(h1));
    __nv_bfloat16 l2 = __float2bfloat16(v.z - __bfloat162float(h2));
    __nv_bfloat16 l3 = __float2bfloat16(v.w - __bfloat162float(h3));
    ushort4 H = {__bfloat16_as_ushort(h0), __bfloat16_as_ushort(h1),
                 __bfloat16_as_ushort(h2), __bfloat16_as_ushort(h3)};
    ushort4 L = {__bfloat16_as_ushort(l0), __bfloat16_as_ushort(l1),
                 __bfloat16_as_ushort(l2), __bfloat16_as_ushort(l3)};
    hi[i] = H;
    lo[i] = L;
}

// ------- strided variant: rows x width slice out of a wider fp32 matrix -----
__global__ void split_strided_kernel(const float* __restrict__ in,
                                     __nv_bfloat16* __restrict__ hi,
                                     __nv_bfloat16* __restrict__ lo,
                                     int srcstride, int srcoff,
                                     int width, int total4)
{
    int i = blockIdx.x * blockDim.x + threadIdx.x;
    if (i >= total4) return;
    int w4 = width >> 2;
    int row = i / w4;
    int j = (i - row * w4) << 2;
    float4 v = *(const float4*)(in + (size_t)row * srcstride + srcoff + j);
    __nv_bfloat16 h0 = __float2bfloat16(v.x);
    __nv_bfloat16 h1 = __float2bfloat16(v.y);
    __nv_bfloat16 h2 = __float2bfloat16(v.z);
    __nv_bfloat16 h3 = __float2bfloat16(v.w);
    ushort4 H = {__bfloat16_as_ushort(h0), __bfloat16_as_ushort(h1),
                 __bfloat16_as_ushort(h2), __bfloat16_as_ushort(h3)};
    ushort4 L = {
        __bfloat16_as_ushort(__float2bfloat16(v.x - __bfloat162float(h0))),
        __bfloat16_as_ushort(__float2bfloat16(v.y - __bfloat162float(h1))),
        __bfloat16_as_ushort(__float2bfloat16(v.z - __bfloat162float(h2))),
        __bfloat16_as_ushort(__float2bfloat16(v.w - __bfloat162float(h3)))};
    *(ushort4*)(hi + (size_t)row * width + j) = H;
    *(ushort4*)(lo + (size_t)row * width + j) = L;
}

// ------------- fp32 [K,N] -> transposed bf16 hi/lo [N,K] --------------------
__global__ __launch_bounds__(256) void splitT_kernel(
    const float* __restrict__ W,
    __nv_bfloat16* __restrict__ hiT, __nv_bfloat16* __restrict__ loT,
    int K, int N)
{
    __shared__ float tile[32][33];
    const int tx = threadIdx.x;
    const int ty = threadIdx.y;
    const int n0 = blockIdx.x * 32;
    const int k0 = blockIdx.y * 32;
    #pragma unroll
    for (int i = 0; i < 4; i++)
        tile[ty + 8*i][tx] = W[(size_t)(k0 + ty + 8*i) * N + n0 + tx];
    __syncthreads();
    #pragma unroll
    for (int i = 0; i < 4; i++) {
        float v = tile[tx][ty + 8*i];
        __nv_bfloat16 h = __float2bfloat16(v);
        __nv_bfloat16 l = __float2bfloat16(v - __bfloat162float(h));
        size_t o = (size_t)(n0 + ty + 8*i) * K + k0 + tx;
        hiT[o] = h;
        loT[o] = l;
    }
}

// ------------- fused RoPE + prescale + bf16 hi/lo split ---------------------
// Reads from the fused qkv buffer (row stride NQKV, column offset coff).
__global__ void rope_split_kernel(const float* __restrict__ src,
                                  __nv_bfloat16* __restrict__ hi,
                                  __nv_bfloat16* __restrict__ lo,
                                  const float* __restrict__ fcos,
                                  const float* __restrict__ fsin,
                                  int nheads, int coff, float prescale,
                                  int total_pairs)
{
    int idx = blockIdx.x * blockDim.x + threadIdx.x;
    if (idx >= total_pairs) return;
    int d = idx & 63;
    int r2 = idx >> 6;                  // (b*S+s)*nheads + h
    int bs = r2 / nheads;
    int h = r2 - bs * nheads;
    int s = bs % SEQ;
    size_t sbase = (size_t)bs * NQKV + coff + h * HD;
    size_t dbase = (size_t)r2 * HD;
    float c  = fcos[s * 64 + d];
    float sn = fsin[s * 64 + d];
    float t1 = src[sbase + d];
    float t2 = src[sbase + 64 + d];
    float r1 = (t1 * c  - t2 * sn) * prescale;
    float rr = (t1 * sn + t2 * c)  * prescale;
    __nv_bfloat16 h1 = __float2bfloat16(r1);
    __nv_bfloat16 h2 = __float2bfloat16(rr);
    hi[dbase + d]      = h1;
    hi[dbase + 64 + d] = h2;
    lo[dbase + d]      = __float2bfloat16(r1 - __bfloat162float(h1));
    lo[dbase + 64 + d] = __float2bfloat16(rr - __bfloat162float(h2));
}

// ---------------- warp-MMA GEMM: C[M,N] = A @ B^T (3-term bf16 split) -------
// CTA tile 128x256, BK=32, 512 threads (16 warps, each 32x64), 3-stage cp.async.
#define BK 32
#define ROWB 80
#define A_TILE_B (128 * ROWB)          // 10240
#define B_TILE_B (256 * ROWB)          // 20480
#define STAGE_B (2 * A_TILE_B + 2 * B_TILE_B)   // 61440
#define GSMEM_BYTES (3 * STAGE_B)               // 184320

__global__ __launch_bounds__(512, 1) void gemm3_kernel(
    const __nv_bfloat16* __restrict__ Ahi, const __nv_bfloat16* __restrict__ Alo,
    const __nv_bfloat16* __restrict__ Bhi, const __nv_bfloat16* __restrict__ Blo,
    float* __restrict__ C, int M, int N, int K)
{
    extern __shared__ char sb[];
    const uint32_t sbase = smem_u32(sb);
    const int tid = threadIdx.x;
    const int wid = tid >> 5;
    const int lid = tid & 31;
    const int wm = wid & 3;              // 4 m-groups of 32 rows
    const int wn = wid >> 2;             // 4 n-groups of 64 cols

    const int row0 = blockIdx.y * 128;
    const int col0 = blockIdx.x * 256;

    const __nv_bfloat16* gp[4] = {
        Ahi + (size_t)row0 * K, Alo + (size_t)row0 * K,
        Bhi + (size_t)col0 * K, Blo + (size_t)col0 * K
    };

    float acc[2][8][4];
    #pragma unroll
    for (int mi = 0; mi < 2; mi++)
        #pragma unroll
        for (int g = 0; g < 8; g++)
            #pragma unroll
            for (int e = 0; e < 4; e++) acc[mi][g][e] = 0.f;

    const int a_row = lid & 15;
    const int a_kx  = (lid >> 4) << 3;
    const int b_row = (lid & 7) + ((lid >> 4) << 3);
    const int b_kx  = ((lid >> 3) & 1) << 3;

    const int nkc = K / BK;

    // prefetch stages 0,1
    #pragma unroll
    for (int ps = 0; ps < 2; ps++) {
        int k0 = ps * BK;
        uint32_t stg = sbase + ps * STAGE_B;
        #pragma unroll
        for (int i = 0; i < 6; i++) {
            int f = tid + i * 512;       // 0..3071
            uint32_t saddr;
            const __nv_bfloat16* g;
            if (f < 1024) {
                int t = f >> 9;          // Ahi / Alo
                int r = (f & 511) >> 2, c = f & 3;
                g = gp[t] + (size_t)r * K + k0 + c * 8;
                saddr = stg + t * A_TILE_B + r * ROWB + c * 16;
            } else {
                int gg = f - 1024;
                int t = gg >> 10;        // Bhi / Blo
                int r = (gg & 1023) >> 2, c = gg & 3;
                g = gp[2 + t] + (size_t)r * K + k0 + c * 8;
                saddr = stg + 2 * A_TILE_B + t * B_TILE_B + r * ROWB + c * 16;
            }
            CP_ASYNC16(saddr, g);
        }
        CP_COMMIT();
    }

    int buf = 0;
    for (int kc = 0; kc < nkc; kc++) {
        if (kc + 2 < nkc) {
            int k0 = (kc + 2) * BK;
            int pb = buf + 2; if (pb >= 3) pb -= 3;
            uint32_t stg = sbase + pb * STAGE_B;
            #pragma unroll
            for (int i = 0; i < 6; i++) {
                int f = tid + i * 512;
                uint32_t saddr;
                const __nv_bfloat16* g;
                if (f < 1024) {
                    int t = f >> 9;
                    int r = (f & 511) >> 2, c = f & 3;
                    g = gp[t] + (size_t)r * K + k0 + c * 8;
                    saddr = stg + t * A_TILE_B + r * ROWB + c * 16;
                } else {
                    int gg = f - 1024;
                    int t = gg >> 10;
                    int r = (gg & 1023) >> 2, c = gg & 3;
                    g = gp[2 + t] + (size_t)r * K + k0 + c * 8;
                    saddr = stg + 2 * A_TILE_B + t * B_TILE_B + r * ROWB + c * 16;
                }
                CP_ASYNC16(saddr, g);
            }
            CP_COMMIT();
            CP_WAIT(2);
        } else if (kc + 1 < nkc) {
            CP_WAIT(1);
        } else {
            CP_WAIT(0);
        }
        __syncthreads();

        const uint32_t st = sbase + buf * STAGE_B;
        #pragma unroll
        for (int ks = 0; ks < 2; ks++) {
            const int k0 = ks * 16;
            uint32_t ah[2][4], al[2][4];
            #pragma unroll
            for (int mi = 0; mi < 2; mi++) {
                uint32_t aoff = (uint32_t)((wm * 32 + mi * 16 + a_row) * ROWB
                                           + (k0 + a_kx) * 2);
                ldsm_x4(ah[mi], st + aoff);
                ldsm_x4(al[mi], st + A_TILE_B + aoff);
            }
            #pragma unroll
            for (int g4 = 0; g4 < 4; g4++) {
                uint32_t bh[4], bl[4];
                uint32_t boff = (uint32_t)((wn * 64 + g4 * 16 + b_row) * ROWB
                                           + (k0 + b_kx) * 2);
                ldsm_x4(bh, st + 2 * A_TILE_B + boff);
                ldsm_x4(bl, st + 2 * A_TILE_B + B_TILE_B + boff);
                #pragma unroll
                for (int mi = 0; mi < 2; mi++) {
                    #pragma unroll
                    for (int sub = 0; sub < 2; sub++) {
                        float* d = acc[mi][g4 * 2 + sub];
                        mma16816(d, ah[mi], bh + sub * 2);
                        mma16816(d, ah[mi], bl + sub * 2);
                        mma16816(d, al[mi], bh + sub * 2);
                    }
                }
            }
        }
        __syncthreads();
        if (++buf == 3) buf = 0;
    }

    const int cr = lid >> 2;
    const int cc = (lid & 3) * 2;
    #pragma unroll
    for (int mi = 0; mi < 2; mi++) {
        #pragma unroll
        for (int g = 0; g < 8; g++) {
            int rg = row0 + wm * 32 + mi * 16 + cr;
            int cg = col0 + wn * 64 + g * 8 + cc;
            float2 v0 = {acc[mi][g][0], acc[mi][g][1]};
            float2 v1 = {acc[mi][g][2], acc[mi][g][3]};
            *(float2*)(C + (size_t)rg * N + cg)       = v0;
            *(float2*)(C + (size_t)(rg + 8) * N + cg) = v1;
        }
    }
}

// ---------------- Flash attention, HMMA (causal, GQA) -----------------------
// Q/K 3-term, P/V 3-term. Writes bf16 hi/lo output directly.
#define FROWB 272
#define FQ_TILE (128 * FROWB)
#define FKV_TILE (64 * FROWB)
#define FSTAGE (4 * FKV_TILE)
#define FSMEM (2 * FQ_TILE + 2 * FSTAGE)   // 208896

__global__ __launch_bounds__(256, 1) void flash_mma_kernel(
    const __nv_bfloat16* __restrict__ Qh, const __nv_bfloat16* __restrict__ Ql,
    const __nv_bfloat16* __restrict__ Kh, const __nv_bfloat16* __restrict__ Kl,
    const __nv_bfloat16* __restrict__ Vh, const __nv_bfloat16* __restrict__ Vl,
    __nv_bfloat16* __restrict__ Ohi, __nv_bfloat16* __restrict__ Olo)
{
    extern __shared__ char sb[];
    const uint32_t smq = smem_u32(sb);
    const uint32_t smkv = smq + 2 * FQ_TILE;

    const int qb  = blockIdx.x;
    const int h   = blockIdx.y;
    const int b   = blockIdx.z;
    const int kvh = h / GROUPS;
    const int tid = threadIdx.x;
    const int wid = tid >> 5;
    const int lid = tid & 31;

    {
        const __nv_bfloat16* qsrc[2] = {
            Qh + ((size_t)(b * SEQ + qb * 128) * NH + h) * HD,
            Ql + ((size_t)(b * SEQ + qb * 128) * NH + h) * HD
        };
        #pragma unroll
        for (int i = 0; i < 16; i++) {
            int chunk = tid + i * 256;
            int t = chunk >> 11;
            int w = chunk & 2047;
            int r = w >> 4, x = w & 15;
            const __nv_bfloat16* g = qsrc[t] + (size_t)r * NH * HD + x * 8;
            CP_ASYNC16(smq + t * FQ_TILE + r * FROWB + x * 16, g);
        }
        CP_COMMIT();
    }

    const __nv_bfloat16* kvsrc[4] = {
        Kh + ((size_t)(b * SEQ) * NKV + kvh) * HD,
        Kl + ((size_t)(b * SEQ) * NKV + kvh) * HD,
        Vh + ((size_t)(b * SEQ) * NKV + kvh) * HD,
        Vl + ((size_t)(b * SEQ) * NKV + kvh) * HD
    };

    const int nkt = 2 * qb + 2;

    {
        #pragma unroll
        for (int i = 0; i < 16; i++) {
            int chunk = tid + i * 256;
            int t = chunk >> 10;
            int w = chunk & 1023;
            int r = w >> 4, x = w & 15;
            const __nv_bfloat16* g = kvsrc[t] + (size_t)r * NKV * HD + x * 8;
            CP_ASYNC16(smkv + t * FKV_TILE + r * FROWB + x * 16, g);
        }
        CP_COMMIT();
    }

    const int Q0 = wid * 16;
    const int r0 = lid >> 2;
    const int c0 = (lid & 3) * 2;
    float m0 = -1e30f, m1 = -1e30f, l0 = 0.f, l1 = 0.f;
    float acc_o[16][4];
    #pragma unroll
    for (int t = 0; t < 16; t++)
        #pragma unroll
        for (int e = 0; e < 4; e++) acc_o[t][e] = 0.f;

    const int a_row = lid & 15;
    const int a_kx  = (lid >> 4) << 3;
    const int b_row = (lid & 7) + ((lid >> 4) << 3);
    const int b_kx  = ((lid >> 3) & 1) << 3;

    for (int kt = 0; kt < nkt; kt++) {
        __syncthreads();
        if (kt + 1 < nkt) {
            int k0r = (kt + 1) * 64;
            uint32_t stg = smkv + ((kt + 1) & 1) * FSTAGE;
            #pragma unroll
            for (int i = 0; i < 16; i++) {
                int chunk = tid + i * 256;
                int t = chunk >> 10;
                int w = chunk & 1023;
                int r = w >> 4, x = w & 15;
                const __nv_bfloat16* g = kvsrc[t]
                    + (size_t)(k0r + r) * NKV * HD + x * 8;
                CP_ASYNC16(stg + t * FKV_TILE + r * FROWB + x * 16, g);
            }
            CP_COMMIT();
            CP_WAIT(1);
        } else {
            CP_WAIT(0);
        }
        __syncthreads();

        const uint32_t skh = smkv + (kt & 1) * FSTAGE;
        const uint32_t skl = skh + FKV_TILE;
        const uint32_t svh = skh + 2 * FKV_TILE;
        const uint32_t svl = skh + 3 * FKV_TILE;

        // ---- S = Q K^T (3-term) ----
        float s_acc[8][4];
        #pragma unroll
        for (int t = 0; t < 8; t++)
            #pragma unroll
            for (int e = 0; e < 4; e++) s_acc[t][e] = 0.f;

        #pragma unroll
        for (int kt8 = 0; kt8 < 8; kt8++) {
            uint32_t ah[4], al[4];
            uint32_t aoff = (uint32_t)((Q0 + a_row) * FROWB + (kt8 * 16 + a_kx) * 2);
            ldsm_x4(ah, smq + aoff);
            ldsm_x4(al, smq + FQ_TILE + aoff);
            #pragma unroll
            for (int ng = 0; ng < 4; ng++) {
                uint32_t bh[4], bl[4];
                uint32_t boff = (uint32_t)((ng * 16 + b_row) * FROWB
                                           + (kt8 * 16 + b_kx) * 2);
                ldsm_x4(bh, skh + boff);
                ldsm_x4(bl, skl + boff);
                #pragma unroll
                for (int sub = 0; sub < 2; sub++) {
                    float* d = s_acc[ng * 2 + sub];
                    mma16816(d, ah, bh + sub * 2);
                    mma16816(d, ah, bl + sub * 2);
                    mma16816(d, al, bh + sub * 2);
                }
            }
        }

        // ---- causal mask ----
        const int k0 = kt * 64;
        const int qg0 = qb * 128 + Q0 + r0;
        if (k0 + 63 > qb * 128 + Q0) {
            #pragma unroll
            for (int t = 0; t < 8; t++) {
                int kc = k0 + t * 8 + c0;
                if (kc     > qg0)     s_acc[t][0] = -1e30f;
                if (kc + 1 > qg0)     s_acc[t][1] = -1e30f;
                if (kc     > qg0 + 8) s_acc[t][2] = -1e30f;
                if (kc + 1 > qg0 + 8) s_acc[t][3] = -1e30f;
            }
        }

        // ---- online softmax (scores pre-scaled by 1/sqrt(d)*log2e) ----
        float mx0 = -1e30f, mx1 = -1e30f;
        #pragma unroll
        for (int t = 0; t < 8; t++) {
            mx0 = fmaxf(mx0, fmaxf(s_acc[t][0], s_acc[t][1]));
            mx1 = fmaxf(mx1, fmaxf(s_acc[t][2], s_acc[t][3]));
        }
        mx0 = fmaxf(mx0, __shfl_xor_sync(0xffffffffu, mx0, 1));
        mx0 = fmaxf(mx0, __shfl_xor_sync(0xffffffffu, mx0, 2));
        mx1 = fmaxf(mx1, __shfl_xor_sync(0xffffffffu, mx1, 1));
        mx1 = fmaxf(mx1, __shfl_xor_sync(0xffffffffu, mx1, 2));
        float mn0 = fmaxf(m0, mx0);
        float mn1 = fmaxf(m1, mx1);
        float e0 = exp2f(m0 - mn0);
        float e1 = exp2f(m1 - mn1);
        float rs0 = 0.f, rs1 = 0.f;
        #pragma unroll
        for (int t = 0; t < 8; t++) {
            s_acc[t][0] = exp2f(s_acc[t][0] - mn0);
            s_acc[t][1] = exp2f(s_acc[t][1] - mn0);
            s_acc[t][2] = exp2f(s_acc[t][2] - mn1);
            s_acc[t][3] = exp2f(s_acc[t][3] - mn1);
            rs0 += s_acc[t][0] + s_acc[t][1];
            rs1 += s_acc[t][2] + s_acc[t][3];
        }
        rs0 += __shfl_xor_sync(0xffffffffu, rs0, 1);
        rs0 += __shfl_xor_sync(0xffffffffu, rs0, 2);
        rs1 += __shfl_xor_sync(0xffffffffu, rs1, 1);
        rs1 += __shfl_xor_sync(0xffffffffu, rs1, 2);
        l0 = l0 * e0 + rs0;
        l1 = l1 * e1 + rs1;
        m0 = mn0;
        m1 = mn1;
        #pragma unroll
        for (int t = 0; t < 16; t++) {
            acc_o[t][0] *= e0;
            acc_o[t][1] *= e0;
            acc_o[t][2] *= e1;
            acc_o[t][3] *= e1;
        }

        // ---- O += P V (3-term: Phi*Vhi + Phi*Vlo + Plo*Vhi) ----
        #pragma unroll
        for (int ktv = 0; ktv < 4; ktv++) {
            uint32_t a[4], ar[4];
            #pragma unroll
            for (int pe = 0; pe < 4; pe++) {
                float x0 = s_acc[2*ktv + (pe >> 1)][(pe & 1) ? 2 : 0];
                float x1 = s_acc[2*ktv + (pe >> 1)][(pe & 1) ? 3 : 1];
                __nv_bfloat162 hh = __floats2bfloat162_rn(x0, x1);
                float q0 = x0 - __bfloat162float(__low2bfloat16(hh));
                float q1 = x1 - __bfloat162float(__high2bfloat16(hh));
                __nv_bfloat162 ll = __floats2bfloat162_rn(q0, q1);
                a[pe]  = *(uint32_t*)&hh;
                ar[pe] = *(uint32_t*)&ll;
            }
            #pragma unroll
            for (int ng = 0; ng < 8; ng++) {
                uint32_t voff = (uint32_t)((ktv * 16 + (lid & 15)) * FROWB
                                           + (ng * 16 + ((lid >> 4) << 3)) * 2);
                uint32_t bh[4], bl[4];
                ldsm_x4_t(bh, svh + voff);
                ldsm_x4_t(bl, svl + voff);
                mma16816(acc_o[ng * 2],     a, bh);
                mma16816(acc_o[ng * 2 + 1], a, bh + 2);
                mma16816(acc_o[ng * 2],     a, bl);
                mma16816(acc_o[ng * 2 + 1], a, bl + 2);
                mma16816(acc_o[ng * 2],     ar, bh);
                mma16816(acc_o[ng * 2 + 1], ar, bh + 2);
            }
        }
    }

    // ---- normalize + write bf16 hi/lo out ----
    const float li0 = 1.f / l0;
    const float li1 = 1.f / l1;
    const size_t obase = ((size_t)(b * SEQ + qb * 128 + Q0) * NH + h) * HD;
    #pragma unroll
    for (int t = 0; t < 16; t++) {
        float e00 = acc_o[t][0] * li0, e01 = acc_o[t][1] * li0;
        float e10 = acc_o[t][2] * li1, e11 = acc_o[t][3] * li1;
        __nv_bfloat162 h0 = __floats2bfloat162_rn(e00, e01);
        __nv_bfloat162 h1 = __floats2bfloat162_rn(e10, e11);
        __nv_bfloat162 l0v = __floats2bfloat162_rn(
            e00 - __bfloat162float(__low2bfloat16(h0)),
            e01 - __bfloat162float(__high2bfloat16(h0)));
        __nv_bfloat162 l1v = __floats2bfloat162_rn(
            e10 - __bfloat162float(__low2bfloat16(h1)),
            e11 - __bfloat162float(__high2bfloat16(h1)));
        size_t o0 = obase + (size_t)r0 * NH * HD + t * 8 + c0;
        size_t o1 = obase + (size_t)(r0 + 8) * NH * HD + t * 8 + c0;
        *(__nv_bfloat162*)(Ohi + o0) = h0;
        *(__nv_bfloat162*)(Olo + o0) = l0v;
        *(__nv_bfloat162*)(Ohi + o1) = h1;
        *(__nv_bfloat162*)(Olo + o1) = l1v;
    }
}

// ---------------- launch ----------------------------------------------------
template <typename T>
static T* sym_addr(const void* sym)
{
    void* p = nullptr;
    cudaGetSymbolAddress(&p, sym);
    return (T*)p;
}

extern "C" void kernel_launch(void* const* d_in, const int* in_sizes, int n_in,
                              void* d_out, int out_size)
{
    const float* x    = (const float*)d_in[0];
    const float* wq   = (const float*)d_in[1];
    const float* wk   = (const float*)d_in[2];
    const float* wv   = (const float*)d_in[3];
    const float* wo   = (const float*)d_in[4];
    const float* fcos = (const float*)d_in[5];
    const float* fsin = (const float*)d_in[6];
    float* out = (float*)d_out;

    float* qkv = sym_addr<float>(g_qkv);
    __nv_bfloat16* xhi  = sym_addr<__nv_bfloat16>(g_xhi);
    __nv_bfloat16* xlo  = sym_addr<__nv_bfloat16>(g_xlo);
    __nv_bfloat16* ahi  = sym_addr<__nv_bfloat16>(g_ahi);
    __nv_bfloat16* alo  = sym_addr<__nv_bfloat16>(g_alo);
    __nv_bfloat16* wqkvh = sym_addr<__nv_bfloat16>(g_wqkvhiT);
    __nv_bfloat16* wqkvl = sym_addr<__nv_bfloat16>(g_wqkvloT);
    __nv_bfloat16* woh  = sym_addr<__nv_bfloat16>(g_wohiT);
    __nv_bfloat16* wol  = sym_addr<__nv_bfloat16>(g_woloT);
    __nv_bfloat16* qh = sym_addr<__nv_bfloat16>(g_qh);
    __nv_bfloat16* ql = sym_addr<__nv_bfloat16>(g_ql);
    __nv_bfloat16* kh = sym_addr<__nv_bfloat16>(g_kh);
    __nv_bfloat16* kl = sym_addr<__nv_bfloat16>(g_kl);
    __nv_bfloat16* vh = sym_addr<__nv_bfloat16>(g_vh);
    __nv_bfloat16* vl = sym_addr<__nv_bfloat16>(g_vl);

    static bool attrs_set = false;
    if (!attrs_set) {
        cudaFuncSetAttribute(gemm3_kernel,
                             cudaFuncAttributeMaxDynamicSharedMemorySize, GSMEM_BYTES);
        cudaFuncSetAttribute(flash_mma_kernel,
                             cudaFuncAttributeMaxDynamicSharedMemorySize, FSMEM);
        attrs_set = true;
    }

    // Split/transpose conversions.
    // Concatenated transposed weight: rows [0,4096)=wq, [4096,5120)=wk, [5120,6144)=wv
    {
        int n4 = MROWS * HID / 4;
        split_kernel<<<(n4 + 255) / 256, 256>>>((const float4*)x,
                                                (ushort4*)xhi, (ushort4*)xlo, n4);
        splitT_kernel<<<dim3(HID/32, HID/32), dim3(32,8)>>>(
            wq, wqkvh, wqkvl, HID, HID);
        splitT_kernel<<<dim3((NKV*HD)/32, HID/32), dim3(32,8)>>>(
            wk, wqkvh + (size_t)HID * HID, wqkvl + (size_t)HID * HID, HID, NKV*HD);
        splitT_kernel<<<dim3((NKV*HD)/32, HID/32), dim3(32,8)>>>(
            wv, wqkvh + (size_t)(HID + NKV*HD) * HID,
                wqkvl + (size_t)(HID + NKV*HD) * HID, HID, NKV*HD);
        splitT_kernel<<<dim3(HID/32, HID/32), dim3(32,8)>>>(wo, woh, wol, HID, HID);
    }

    // Fused QKV projection (tensor cores, 3-term bf16): [2048, 6144]
    gemm3_kernel<<<dim3(NQKV/256, MROWS/128), 512, GSMEM_BYTES>>>(
        xhi, xlo, wqkvh, wqkvl, qkv, MROWS, NQKV, HID);

    // RoPE + prescale + split (Q, K); plain strided split (V)
    {
        const float qscale = 0.08838834764831845f * 1.4426950408889634f; // 1/sqrt(128)*log2e
        int pq = MROWS * NH * 64;
        int pk = MROWS * NKV * 64;
        rope_split_kernel<<<(pq + 255) / 256, 256>>>(
            qkv, qh, ql, fcos, fsin, NH, 0, qscale, pq);
        rope_split_kernel<<<(pk + 255) / 256, 256>>>(
            qkv, kh, kl, fcos, fsin, NKV, HID, 1.0f, pk);
        int t4 = MROWS * NKV * HD / 4;
        split_strided_kernel<<<(t4 + 255) / 256, 256>>>(
            qkv, vh, vl, NQKV, HID + NKV*HD, NKV*HD, t4);
    }

    // Flash attention (HMMA), writes bf16 hi/lo directly
    flash_mma_kernel<<<dim3(SEQ / 128, NH, BATCH), 256, FSMEM>>>(
        qh, ql, kh, kl, vh, vl, ahi, alo);

    // Output projection
    gemm3_kernel<<<dim3(HID/256, MROWS/128), 512, GSMEM_BYTES>>>(
        ahi, alo, woh, wol, out, MROWS, HID, HID);
}

// round 8
// speedup vs baseline: 1.2473x; 1.1007x over previous
#include <cuda_runtime.h>
#include <cuda_bf16.h>
#include <math.h>
#include <stdint.h>

// Problem constants
#define BATCH 2
#define SEQ   1024
#define HID   4096
#define NH    32
#define NKV   8
#define HD    128
#define MROWS (BATCH*SEQ)          // 2048
#define GROUPS (NH/NKV)            // 4
#define NQKV  (HID + 2*NKV*HD)     // 6144 (q 0..4095, k 4096..5119, v 5120..6143)
#define VCOL0 (HID + NKV*HD)       // 5120
#define VW    (NKV*HD)             // 1024

// ======================= warp MMA helpers (sm_80+ path) =====================
__device__ __forceinline__ uint32_t smem_u32(const void* p) {
    uint32_t a;
    asm("{ .reg .u64 t; cvta.to.shared.u64 t, %1; cvt.u32.u64 %0, t; }"
        : "=r"(a) : "l"(p));
    return a;
}

__device__ __forceinline__ void ldsm_x4(uint32_t* r, uint32_t addr) {
    asm volatile("ldmatrix.sync.aligned.m8n8.x4.shared.b16 {%0,%1,%2,%3}, [%4];"
                 : "=r"(r[0]), "=r"(r[1]), "=r"(r[2]), "=r"(r[3]) : "r"(addr));
}
__device__ __forceinline__ void ldsm_x4_t(uint32_t* r, uint32_t addr) {
    asm volatile("ldmatrix.sync.aligned.m8n8.x4.trans.shared.b16 {%0,%1,%2,%3}, [%4];"
                 : "=r"(r[0]), "=r"(r[1]), "=r"(r[2]), "=r"(r[3]) : "r"(addr));
}

__device__ __forceinline__ void mma16816(float* d, const uint32_t* a,
                                         const uint32_t* b) {
    asm volatile("mma.sync.aligned.m16n8k16.row.col.f32.bf16.bf16.f32 "
                 "{%0,%1,%2,%3}, {%4,%5,%6,%7}, {%8,%9}, {%0,%1,%2,%3};"
                 : "+f"(d[0]), "+f"(d[1]), "+f"(d[2]), "+f"(d[3])
                 : "r"(a[0]), "r"(a[1]), "r"(a[2]), "r"(a[3]),
                   "r"(b[0]), "r"(b[1]));
}

#define CP_ASYNC16(smem, gptr) \
    asm volatile("cp.async.cg.shared.global [%0], [%1], 16;" \
                 :: "r"(smem), "l"(gptr))
#define CP_COMMIT() asm volatile("cp.async.commit_group;" ::: "memory")
#define CP_WAIT(N)  asm volatile("cp.async.wait_group %0;" :: "n"(N) : "memory")

// ---------------- scratch (device globals; no cudaMalloc allowed) ----------
__device__ float g_qkv[(size_t)MROWS * NQKV];       // fused QKV output (fp32; V region unused)

__device__ __nv_bfloat16 g_xhi[(size_t)MROWS * HID];
__device__ __nv_bfloat16 g_xlo[(size_t)MROWS * HID];
__device__ __nv_bfloat16 g_ahi[(size_t)MROWS * HID];
__device__ __nv_bfloat16 g_alo[(size_t)MROWS * HID];
__device__ __nv_bfloat16 g_wqkvhiT[(size_t)NQKV * HID];   // [6144, 4096]
__device__ __nv_bfloat16 g_wqkvloT[(size_t)NQKV * HID];
__device__ __nv_bfloat16 g_wohiT[(size_t)HID * HID];
__device__ __nv_bfloat16 g_woloT[(size_t)HID * HID];

// bf16 attention operands (post-RoPE)
__device__ __nv_bfloat16 g_qh[(size_t)MROWS * NH * HD];
__device__ __nv_bfloat16 g_ql[(size_t)MROWS * NH * HD];
__device__ __nv_bfloat16 g_kh[(size_t)MROWS * NKV * HD];
__device__ __nv_bfloat16 g_kl[(size_t)MROWS * NKV * HD];
__device__ __nv_bfloat16 g_vh[(size_t)MROWS * NKV * HD];
__device__ __nv_bfloat16 g_vl[(size_t)MROWS * NKV * HD];

// ---------------- fp32 -> bf16 hi/lo split (elementwise) --------------------
__global__ void split_kernel(const float4* __restrict__ in,
                             ushort4* __restrict__ hi,
                             ushort4* __restrict__ lo, int n4)
{
    int i = blockIdx.x * blockDim.x + threadIdx.x;
    if (i >= n4) return;
    float4 v = in[i];
    __nv_bfloat16 h0 = __float2bfloat16(v.x);
    __nv_bfloat16 h1 = __float2bfloat16(v.y);
    __nv_bfloat16 h2 = __float2bfloat16(v.z);
    __nv_bfloat16 h3 = __float2bfloat16(v.w);
    __nv_bfloat16 l0 = __float2bfloat16(v.x - __bfloat162float(h0));
    __nv_bfloat16 l1 = __float2bfloat16(v.y - __bfloat162float(h1));
    __nv_bfloat16 l2 = __float2bfloat16(v.z - __bfloat162float(h2));
    __nv_bfloat16 l3 = __float2bfloat16(v.w - __bfloat162float(h3));
    ushort4 H = {__bfloat16_as_ushort(h0), __bfloat16_as_ushort(h1),
                 __bfloat16_as_ushort(h2), __bfloat16_as_ushort(h3)};
    ushort4 L = {__bfloat16_as_ushort(l0), __bfloat16_as_ushort(l1),
                 __bfloat16_as_ushort(l2), __bfloat16_as_ushort(l3)};
    hi[i] = H;
    lo[i] = L;
}

// ------------- fp32 [K,N] -> transposed bf16 hi/lo [N,K] --------------------
__global__ __launch_bounds__(256) void splitT_kernel(
    const float* __restrict__ W,
    __nv_bfloat16* __restrict__ hiT, __nv_bfloat16* __restrict__ loT,
    int K, int N)
{
    __shared__ float tile[32][33];
    const int tx = threadIdx.x;
    const int ty = threadIdx.y;
    const int n0 = blockIdx.x * 32;
    const int k0 = blockIdx.y * 32;
    #pragma unroll
    for (int i = 0; i < 4; i++)
        tile[ty + 8*i][tx] = W[(size_t)(k0 + ty + 8*i) * N + n0 + tx];
    __syncthreads();
    #pragma unroll
    for (int i = 0; i < 4; i++) {
        float v = tile[tx][ty + 8*i];
        __nv_bfloat16 h = __float2bfloat16(v);
        __nv_bfloat16 l = __float2bfloat16(v - __bfloat162float(h));
        size_t o = (size_t)(n0 + ty + 8*i) * K + k0 + tx;
        hiT[o] = h;
        loT[o] = l;
    }
}

// ------------- fused RoPE + prescale + bf16 hi/lo split ---------------------
__global__ void rope_split_kernel(const float* __restrict__ src,
                                  __nv_bfloat16* __restrict__ hi,
                                  __nv_bfloat16* __restrict__ lo,
                                  const float* __restrict__ fcos,
                                  const float* __restrict__ fsin,
                                  int nheads, int coff, float prescale,
                                  int total_pairs)
{
    int idx = blockIdx.x * blockDim.x + threadIdx.x;
    if (idx >= total_pairs) return;
    int d = idx & 63;
    int r2 = idx >> 6;                  // (b*S+s)*nheads + h
    int bs = r2 / nheads;
    int h = r2 - bs * nheads;
    int s = bs % SEQ;
    size_t sbase = (size_t)bs * NQKV + coff + h * HD;
    size_t dbase = (size_t)r2 * HD;
    float c  = fcos[s * 64 + d];
    float sn = fsin[s * 64 + d];
    float t1 = src[sbase + d];
    float t2 = src[sbase + 64 + d];
    float r1 = (t1 * c  - t2 * sn) * prescale;
    float rr = (t1 * sn + t2 * c)  * prescale;
    __nv_bfloat16 h1 = __float2bfloat16(r1);
    __nv_bfloat16 h2 = __float2bfloat16(rr);
    hi[dbase + d]      = h1;
    hi[dbase + 64 + d] = h2;
    lo[dbase + d]      = __float2bfloat16(r1 - __bfloat162float(h1));
    lo[dbase + 64 + d] = __float2bfloat16(rr - __bfloat162float(h2));
}

// ---------------- warp-MMA GEMM: C[M,N] = A @ B^T (3-term bf16 split) -------
// CTA tile 128x256, BK=64, 512 threads (16 warps, each 32x64), 2-stage cp.async.
// Columns >= vcol0 are written as bf16 hi/lo to Vhi/Vlo instead of fp32 C.
#define BK 64
#define ROWB 144
#define A_TILE_B (128 * ROWB)          // 18432
#define B_TILE_B (256 * ROWB)          // 36864
#define STAGE_B (2 * A_TILE_B + 2 * B_TILE_B)   // 110592
#define GSMEM_BYTES (2 * STAGE_B)               // 221184

__global__ __launch_bounds__(512, 1) void gemm3_kernel(
    const __nv_bfloat16* __restrict__ Ahi, const __nv_bfloat16* __restrict__ Alo,
    const __nv_bfloat16* __restrict__ Bhi, const __nv_bfloat16* __restrict__ Blo,
    float* __restrict__ C,
    __nv_bfloat16* __restrict__ Vhi, __nv_bfloat16* __restrict__ Vlo,
    int vcol0, int M, int N, int K)
{
    extern __shared__ char sb[];
    const uint32_t sbase = smem_u32(sb);
    const int tid = threadIdx.x;
    const int wid = tid >> 5;
    const int lid = tid & 31;
    const int wm = wid & 3;              // 4 m-groups of 32 rows
    const int wn = wid >> 2;             // 4 n-groups of 64 cols

    const int row0 = blockIdx.y * 128;
    const int col0 = blockIdx.x * 256;

    const __nv_bfloat16* gp[4] = {
        Ahi + (size_t)row0 * K, Alo + (size_t)row0 * K,
        Bhi + (size_t)col0 * K, Blo + (size_t)col0 * K
    };

    float acc[2][8][4];
    #pragma unroll
    for (int mi = 0; mi < 2; mi++)
        #pragma unroll
        for (int g = 0; g < 8; g++)
            #pragma unroll
            for (int e = 0; e < 4; e++) acc[mi][g][e] = 0.f;

    const int a_row = lid & 15;
    const int a_kx  = (lid >> 4) << 3;
    const int b_row = (lid & 7) + ((lid >> 4) << 3);
    const int b_kx  = ((lid >> 3) & 1) << 3;

    const int nkc = K / BK;              // 64

    // prefetch stage 0 (6144 x 16B chunks, 12 per thread)
    {
        #pragma unroll
        for (int i = 0; i < 12; i++) {
            int f = tid + i * 512;
            uint32_t saddr;
            const __nv_bfloat16* g;
            if (f < 2048) {
                int t = f >> 10;
                int w = f & 1023;
                int r = w >> 3, c = w & 7;
                g = gp[t] + (size_t)r * K + c * 8;
                saddr = sbase + t * A_TILE_B + r * ROWB + c * 16;
            } else {
                int gg = f - 2048;
                int t = gg >> 11;
                int w = gg & 2047;
                int r = w >> 3, c = w & 7;
                g = gp[2 + t] + (size_t)r * K + c * 8;
                saddr = sbase + 2 * A_TILE_B + t * B_TILE_B + r * ROWB + c * 16;
            }
            CP_ASYNC16(saddr, g);
        }
        CP_COMMIT();
    }

    int buf = 0;
    for (int kc = 0; kc < nkc; kc++) {
        if (kc + 1 < nkc) {
            int k0 = (kc + 1) * BK;
            uint32_t stg = sbase + (buf ^ 1) * STAGE_B;
            #pragma unroll
            for (int i = 0; i < 12; i++) {
                int f = tid + i * 512;
                uint32_t saddr;
                const __nv_bfloat16* g;
                if (f < 2048) {
                    int t = f >> 10;
                    int w = f & 1023;
                    int r = w >> 3, c = w & 7;
                    g = gp[t] + (size_t)r * K + k0 + c * 8;
                    saddr = stg + t * A_TILE_B + r * ROWB + c * 16;
                } else {
                    int gg = f - 2048;
                    int t = gg >> 11;
                    int w = gg & 2047;
                    int r = w >> 3, c = w & 7;
                    g = gp[2 + t] + (size_t)r * K + k0 + c * 8;
                    saddr = stg + 2 * A_TILE_B + t * B_TILE_B + r * ROWB + c * 16;
                }
                CP_ASYNC16(saddr, g);
            }
            CP_COMMIT();
            CP_WAIT(1);
        } else {
            CP_WAIT(0);
        }
        __syncthreads();

        const uint32_t st = sbase + buf * STAGE_B;
        #pragma unroll
        for (int ks = 0; ks < 4; ks++) {
            const int k0 = ks * 16;
            uint32_t ah[2][4], al[2][4];
            #pragma unroll
            for (int mi = 0; mi < 2; mi++) {
                uint32_t aoff = (uint32_t)((wm * 32 + mi * 16 + a_row) * ROWB
                                           + (k0 + a_kx) * 2);
                ldsm_x4(ah[mi], st + aoff);
                ldsm_x4(al[mi], st + A_TILE_B + aoff);
            }
            #pragma unroll
            for (int g4 = 0; g4 < 4; g4++) {
                uint32_t bh[4], bl[4];
                uint32_t boff = (uint32_t)((wn * 64 + g4 * 16 + b_row) * ROWB
                                           + (k0 + b_kx) * 2);
                ldsm_x4(bh, st + 2 * A_TILE_B + boff);
                ldsm_x4(bl, st + 2 * A_TILE_B + B_TILE_B + boff);
                #pragma unroll
                for (int mi = 0; mi < 2; mi++) {
                    #pragma unroll
                    for (int sub = 0; sub < 2; sub++) {
                        float* d = acc[mi][g4 * 2 + sub];
                        mma16816(d, ah[mi], bh + sub * 2);
                        mma16816(d, ah[mi], bl + sub * 2);
                        mma16816(d, al[mi], bh + sub * 2);
                    }
                }
            }
        }
        __syncthreads();
        buf ^= 1;
    }

    const int cr = lid >> 2;
    const int cc = (lid & 3) * 2;
    #pragma unroll
    for (int mi = 0; mi < 2; mi++) {
        #pragma unroll
        for (int g = 0; g < 8; g++) {
            int rg = row0 + wm * 32 + mi * 16 + cr;
            int cg = col0 + wn * 64 + g * 8 + cc;
            if (cg >= vcol0) {
                int vc = cg - vcol0;
                #pragma unroll
                for (int half = 0; half < 2; half++) {
                    float e0 = acc[mi][g][half * 2];
                    float e1 = acc[mi][g][half * 2 + 1];
                    __nv_bfloat162 h = __floats2bfloat162_rn(e0, e1);
                    float r0 = e0 - __bfloat162float(__low2bfloat16(h));
                    float r1 = e1 - __bfloat162float(__high2bfloat16(h));
                    __nv_bfloat162 l = __floats2bfloat162_rn(r0, r1);
                    size_t o = (size_t)(rg + half * 8) * VW + vc;
                    *(__nv_bfloat162*)(Vhi + o) = h;
                    *(__nv_bfloat162*)(Vlo + o) = l;
                }
            } else {
                float2 v0 = {acc[mi][g][0], acc[mi][g][1]};
                float2 v1 = {acc[mi][g][2], acc[mi][g][3]};
                *(float2*)(C + (size_t)rg * N + cg)       = v0;
                *(float2*)(C + (size_t)(rg + 8) * N + cg) = v1;
            }
        }
    }
}

// ---------------- Flash attention, HMMA (causal, GQA) -----------------------
// Q/K 3-term, P/V 3-term. Q fragments cached in registers. Heavy tiles first.
#define FROWB 272
#define FQ_TILE (128 * FROWB)
#define FKV_TILE (64 * FROWB)
#define FSTAGE (4 * FKV_TILE)
#define FSMEM (2 * FQ_TILE + 2 * FSTAGE)   // 208896

__global__ __launch_bounds__(256, 1) void flash_mma_kernel(
    const __nv_bfloat16* __restrict__ Qh, const __nv_bfloat16* __restrict__ Ql,
    const __nv_bfloat16* __restrict__ Kh, const __nv_bfloat16* __restrict__ Kl,
    const __nv_bfloat16* __restrict__ Vh, const __nv_bfloat16* __restrict__ Vl,
    __nv_bfloat16* __restrict__ Ohi, __nv_bfloat16* __restrict__ Olo)
{
    extern __shared__ char sb[];
    const uint32_t smq = smem_u32(sb);
    const uint32_t smkv = smq + 2 * FQ_TILE;

    const int qb  = (int)gridDim.x - 1 - (int)blockIdx.x;   // heavy first
    const int h   = blockIdx.y;
    const int b   = blockIdx.z;
    const int kvh = h / GROUPS;
    const int tid = threadIdx.x;
    const int wid = tid >> 5;
    const int lid = tid & 31;

    {
        const __nv_bfloat16* qsrc[2] = {
            Qh + ((size_t)(b * SEQ + qb * 128) * NH + h) * HD,
            Ql + ((size_t)(b * SEQ + qb * 128) * NH + h) * HD
        };
        #pragma unroll
        for (int i = 0; i < 16; i++) {
            int chunk = tid + i * 256;
            int t = chunk >> 11;
            int w = chunk & 2047;
            int r = w >> 4, x = w & 15;
            const __nv_bfloat16* g = qsrc[t] + (size_t)r * NH * HD + x * 8;
            CP_ASYNC16(smq + t * FQ_TILE + r * FROWB + x * 16, g);
        }
        CP_COMMIT();
    }

    const __nv_bfloat16* kvsrc[4] = {
        Kh + ((size_t)(b * SEQ) * NKV + kvh) * HD,
        Kl + ((size_t)(b * SEQ) * NKV + kvh) * HD,
        Vh + ((size_t)(b * SEQ) * NKV + kvh) * HD,
        Vl + ((size_t)(b * SEQ) * NKV + kvh) * HD
    };

    const int nkt = 2 * qb + 2;

    {
        #pragma unroll
        for (int i = 0; i < 16; i++) {
            int chunk = tid + i * 256;
            int t = chunk >> 10;
            int w = chunk & 1023;
            int r = w >> 4, x = w & 15;
            const __nv_bfloat16* g = kvsrc[t] + (size_t)r * NKV * HD + x * 8;
            CP_ASYNC16(smkv + t * FKV_TILE + r * FROWB + x * 16, g);
        }
        CP_COMMIT();
    }

    const int Q0 = wid * 16;
    const int r0 = lid >> 2;
    const int c0 = (lid & 3) * 2;
    const int a_row = lid & 15;
    const int a_kx  = (lid >> 4) << 3;
    const int b_row = (lid & 7) + ((lid >> 4) << 3);
    const int b_kx  = ((lid >> 3) & 1) << 3;

    // wait for Q + KV0, then cache Q fragments in registers
    CP_WAIT(0);
    __syncthreads();
    uint32_t qf_h[8][4], qf_l[8][4];
    #pragma unroll
    for (int kt8 = 0; kt8 < 8; kt8++) {
        uint32_t aoff = (uint32_t)((Q0 + a_row) * FROWB + (kt8 * 16 + a_kx) * 2);
        ldsm_x4(qf_h[kt8], smq + aoff);
        ldsm_x4(qf_l[kt8], smq + FQ_TILE + aoff);
    }

    float m0 = -1e30f, m1 = -1e30f, l0 = 0.f, l1 = 0.f;
    float acc_o[16][4];
    #pragma unroll
    for (int t = 0; t < 16; t++)
        #pragma unroll
        for (int e = 0; e < 4; e++) acc_o[t][e] = 0.f;

    for (int kt = 0; kt < nkt; kt++) {
        __syncthreads();
        if (kt + 1 < nkt) {
            int k0r = (kt + 1) * 64;
            uint32_t stg = smkv + ((kt + 1) & 1) * FSTAGE;
            #pragma unroll
            for (int i = 0; i < 16; i++) {
                int chunk = tid + i * 256;
                int t = chunk >> 10;
                int w = chunk & 1023;
                int r = w >> 4, x = w & 15;
                const __nv_bfloat16* g = kvsrc[t]
                    + (size_t)(k0r + r) * NKV * HD + x * 8;
                CP_ASYNC16(stg + t * FKV_TILE + r * FROWB + x * 16, g);
            }
            CP_COMMIT();
            CP_WAIT(1);
        } else {
            CP_WAIT(0);
        }
        __syncthreads();

        const uint32_t skh = smkv + (kt & 1) * FSTAGE;
        const uint32_t skl = skh + FKV_TILE;
        const uint32_t svh = skh + 2 * FKV_TILE;
        const uint32_t svl = skh + 3 * FKV_TILE;

        // ---- S = Q K^T (3-term) ----
        float s_acc[8][4];
        #pragma unroll
        for (int t = 0; t < 8; t++)
            #pragma unroll
            for (int e = 0; e < 4; e++) s_acc[t][e] = 0.f;

        #pragma unroll
        for (int kt8 = 0; kt8 < 8; kt8++) {
            #pragma unroll
            for (int ng = 0; ng < 4; ng++) {
                uint32_t bh[4], bl[4];
                uint32_t boff = (uint32_t)((ng * 16 + b_row) * FROWB
                                           + (kt8 * 16 + b_kx) * 2);
                ldsm_x4(bh, skh + boff);
                ldsm_x4(bl, skl + boff);
                #pragma unroll
                for (int sub = 0; sub < 2; sub++) {
                    float* d = s_acc[ng * 2 + sub];
                    mma16816(d, qf_h[kt8], bh + sub * 2);
                    mma16816(d, qf_h[kt8], bl + sub * 2);
                    mma16816(d, qf_l[kt8], bh + sub * 2);
                }
            }
        }

        // ---- causal mask ----
        const int k0 = kt * 64;
        const int qg0 = qb * 128 + Q0 + r0;
        if (k0 + 63 > qb * 128 + Q0) {
            #pragma unroll
            for (int t = 0; t < 8; t++) {
                int kc = k0 + t * 8 + c0;
                if (kc     > qg0)     s_acc[t][0] = -1e30f;
                if (kc + 1 > qg0)     s_acc[t][1] = -1e30f;
                if (kc     > qg0 + 8) s_acc[t][2] = -1e30f;
                if (kc + 1 > qg0 + 8) s_acc[t][3] = -1e30f;
            }
        }

        // ---- online softmax (scores pre-scaled by 1/sqrt(d)*log2e) ----
        float mx0 = -1e30f, mx1 = -1e30f;
        #pragma unroll
        for (int t = 0; t < 8; t++) {
            mx0 = fmaxf(mx0, fmaxf(s_acc[t][0], s_acc[t][1]));
            mx1 = fmaxf(mx1, fmaxf(s_acc[t][2], s_acc[t][3]));
        }
        mx0 = fmaxf(mx0, __shfl_xor_sync(0xffffffffu, mx0, 1));
        mx0 = fmaxf(mx0, __shfl_xor_sync(0xffffffffu, mx0, 2));
        mx1 = fmaxf(mx1, __shfl_xor_sync(0xffffffffu, mx1, 1));
        mx1 = fmaxf(mx1, __shfl_xor_sync(0xffffffffu, mx1, 2));
        float mn0 = fmaxf(m0, mx0);
        float mn1 = fmaxf(m1, mx1);
        float e0 = exp2f(m0 - mn0);
        float e1 = exp2f(m1 - mn1);
        float rs0 = 0.f, rs1 = 0.f;
        #pragma unroll
        for (int t = 0; t < 8; t++) {
            s_acc[t][0] = exp2f(s_acc[t][0] - mn0);
            s_acc[t][1] = exp2f(s_acc[t][1] - mn0);
            s_acc[t][2] = exp2f(s_acc[t][2] - mn1);
            s_acc[t][3] = exp2f(s_acc[t][3] - mn1);
            rs0 += s_acc[t][0] + s_acc[t][1];
            rs1 += s_acc[t][2] + s_acc[t][3];
        }
        rs0 += __shfl_xor_sync(0xffffffffu, rs0, 1);
        rs0 += __shfl_xor_sync(0xffffffffu, rs0, 2);
        rs1 += __shfl_xor_sync(0xffffffffu, rs1, 1);
        rs1 += __shfl_xor_sync(0xffffffffu, rs1, 2);
        l0 = l0 * e0 + rs0;
        l1 = l1 * e1 + rs1;
        m0 = mn0;
        m1 = mn1;
        #pragma unroll
        for (int t = 0; t < 16; t++) {
            acc_o[t][0] *= e0;
            acc_o[t][1] *= e0;
            acc_o[t][2] *= e1;
            acc_o[t][3] *= e1;
        }

        // ---- O += P V (3-term: Phi*Vhi + Phi*Vlo + Plo*Vhi) ----
        #pragma unroll
        for (int ktv = 0; ktv < 4; ktv++) {
            uint32_t a[4], ar[4];
            #pragma unroll
            for (int pe = 0; pe < 4; pe++) {
                float x0 = s_acc[2*ktv + (pe >> 1)][(pe & 1) ? 2 : 0];
                float x1 = s_acc[2*ktv + (pe >> 1)][(pe & 1) ? 3 : 1];
                __nv_bfloat162 hh = __floats2bfloat162_rn(x0, x1);
                float q0 = x0 - __bfloat162float(__low2bfloat16(hh));
                float q1 = x1 - __bfloat162float(__high2bfloat16(hh));
                __nv_bfloat162 ll = __floats2bfloat162_rn(q0, q1);
                a[pe]  = *(uint32_t*)&hh;
                ar[pe] = *(uint32_t*)&ll;
            }
            #pragma unroll
            for (int ng = 0; ng < 8; ng++) {
                uint32_t voff = (uint32_t)((ktv * 16 + (lid & 15)) * FROWB
                                           + (ng * 16 + ((lid >> 4) << 3)) * 2);
                uint32_t bh[4], bl[4];
                ldsm_x4_t(bh, svh + voff);
                ldsm_x4_t(bl, svl + voff);
                mma16816(acc_o[ng * 2],     a, bh);
                mma16816(acc_o[ng * 2 + 1], a, bh + 2);
                mma16816(acc_o[ng * 2],     a, bl);
                mma16816(acc_o[ng * 2 + 1], a, bl + 2);
                mma16816(acc_o[ng * 2],     ar, bh);
                mma16816(acc_o[ng * 2 + 1], ar, bh + 2);
            }
        }
    }

    // ---- normalize + write bf16 hi/lo out ----
    const float li0 = 1.f / l0;
    const float li1 = 1.f / l1;
    const size_t obase = ((size_t)(b * SEQ + qb * 128 + Q0) * NH + h) * HD;
    #pragma unroll
    for (int t = 0; t < 16; t++) {
        float e00 = acc_o[t][0] * li0, e01 = acc_o[t][1] * li0;
        float e10 = acc_o[t][2] * li1, e11 = acc_o[t][3] * li1;
        __nv_bfloat162 h0 = __floats2bfloat162_rn(e00, e01);
        __nv_bfloat162 h1 = __floats2bfloat162_rn(e10, e11);
        __nv_bfloat162 l0v = __floats2bfloat162_rn(
            e00 - __bfloat162float(__low2bfloat16(h0)),
            e01 - __bfloat162float(__high2bfloat16(h0)));
        __nv_bfloat162 l1v = __floats2bfloat162_rn(
            e10 - __bfloat162float(__low2bfloat16(h1)),
            e11 - __bfloat162float(__high2bfloat16(h1)));
        size_t o0 = obase + (size_t)r0 * NH * HD + t * 8 + c0;
        size_t o1 = obase + (size_t)(r0 + 8) * NH * HD + t * 8 + c0;
        *(__nv_bfloat162*)(Ohi + o0) = h0;
        *(__nv_bfloat162*)(Olo + o0) = l0v;
        *(__nv_bfloat162*)(Ohi + o1) = h1;
        *(__nv_bfloat162*)(Olo + o1) = l1v;
    }
}

// ---------------- launch ----------------------------------------------------
template <typename T>
static T* sym_addr(const void* sym)
{
    void* p = nullptr;
    cudaGetSymbolAddress(&p, sym);
    return (T*)p;
}

extern "C" void kernel_launch(void* const* d_in, const int* in_sizes, int n_in,
                              void* d_out, int out_size)
{
    const float* x    = (const float*)d_in[0];
    const float* wq   = (const float*)d_in[1];
    const float* wk   = (const float*)d_in[2];
    const float* wv   = (const float*)d_in[3];
    const float* wo   = (const float*)d_in[4];
    const float* fcos = (const float*)d_in[5];
    const float* fsin = (const float*)d_in[6];
    float* out = (float*)d_out;

    float* qkv = sym_addr<float>(g_qkv);
    __nv_bfloat16* xhi  = sym_addr<__nv_bfloat16>(g_xhi);
    __nv_bfloat16* xlo  = sym_addr<__nv_bfloat16>(g_xlo);
    __nv_bfloat16* ahi  = sym_addr<__nv_bfloat16>(g_ahi);
    __nv_bfloat16* alo  = sym_addr<__nv_bfloat16>(g_alo);
    __nv_bfloat16* wqkvh = sym_addr<__nv_bfloat16>(g_wqkvhiT);
    __nv_bfloat16* wqkvl = sym_addr<__nv_bfloat16>(g_wqkvloT);
    __nv_bfloat16* woh  = sym_addr<__nv_bfloat16>(g_wohiT);
    __nv_bfloat16* wol  = sym_addr<__nv_bfloat16>(g_woloT);
    __nv_bfloat16* qh = sym_addr<__nv_bfloat16>(g_qh);
    __nv_bfloat16* ql = sym_addr<__nv_bfloat16>(g_ql);
    __nv_bfloat16* kh = sym_addr<__nv_bfloat16>(g_kh);
    __nv_bfloat16* kl = sym_addr<__nv_bfloat16>(g_kl);
    __nv_bfloat16* vh = sym_addr<__nv_bfloat16>(g_vh);
    __nv_bfloat16* vl = sym_addr<__nv_bfloat16>(g_vl);

    static bool attrs_set = false;
    if (!attrs_set) {
        cudaFuncSetAttribute(gemm3_kernel,
                             cudaFuncAttributeMaxDynamicSharedMemorySize, GSMEM_BYTES);
        cudaFuncSetAttribute(flash_mma_kernel,
                             cudaFuncAttributeMaxDynamicSharedMemorySize, FSMEM);
        attrs_set = true;
    }

    // Split/transpose conversions.
    {
        int n4 = MROWS * HID / 4;
        split_kernel<<<(n4 + 255) / 256, 256>>>((const float4*)x,
                                                (ushort4*)xhi, (ushort4*)xlo, n4);
        splitT_kernel<<<dim3(HID/32, HID/32), dim3(32,8)>>>(
            wq, wqkvh, wqkvl, HID, HID);
        splitT_kernel<<<dim3((NKV*HD)/32, HID/32), dim3(32,8)>>>(
            wk, wqkvh + (size_t)HID * HID, wqkvl + (size_t)HID * HID, HID, NKV*HD);
        splitT_kernel<<<dim3((NKV*HD)/32, HID/32), dim3(32,8)>>>(
            wv, wqkvh + (size_t)VCOL0 * HID, wqkvl + (size_t)VCOL0 * HID, HID, NKV*HD);
        splitT_kernel<<<dim3(HID/32, HID/32), dim3(32,8)>>>(wo, woh, wol, HID, HID);
    }

    // Fused QKV projection; V columns go straight to bf16 hi/lo
    gemm3_kernel<<<dim3(NQKV/256, MROWS/128), 512, GSMEM_BYTES>>>(
        xhi, xlo, wqkvh, wqkvl, qkv, vh, vl, VCOL0, MROWS, NQKV, HID);

    // RoPE + prescale + split (Q, K)
    {
        const float qscale = 0.08838834764831845f * 1.4426950408889634f; // 1/sqrt(128)*log2e
        int pq = MROWS * NH * 64;
        int pk = MROWS * NKV * 64;
        rope_split_kernel<<<(pq + 255) / 256, 256>>>(
            qkv, qh, ql, fcos, fsin, NH, 0, qscale, pq);
        rope_split_kernel<<<(pk + 255) / 256, 256>>>(
            qkv, kh, kl, fcos, fsin, NKV, HID, 1.0f, pk);
    }

    // Flash attention (HMMA), writes bf16 hi/lo directly
    flash_mma_kernel<<<dim3(SEQ / 128, NH, BATCH), 256, FSMEM>>>(
        qh, ql, kh, kl, vh, vl, ahi, alo);

    // Output projection (no V region)
    gemm3_kernel<<<dim3(HID/256, MROWS/128), 512, GSMEM_BYTES>>>(
        ahi, alo, woh, wol, out, nullptr, nullptr, 1 << 30, MROWS, HID, HID);
}